// round 15
// baseline (speedup 1.0000x reference)
#include <cuda_runtime.h>
#include <cuda_fp16.h>
#include <math.h>
#include <stdint.h>

// ---------------- scratch (no allocation allowed) ----------------
__device__ __half g_hs[6400000];   // 50000 x 128 halves (256B-aligned rows)
__device__ float  g_acc[5000000];  // 50000 x 100 fp32 (layer-1 input)
__device__ float  g_dinv[50048];
__device__ int    g_cnt[50048];    // statically zero; re-zeroed by scan23 each call
__device__ int    g_rowptr[50049];
__device__ int    g_off[50049];
__device__ int    g_adj[800064];
__device__ int    g_bsum[256];
__device__ float  g_partials[512];
__device__ float  g_norm2;

// ---------------- ||x||^2 partial sums (s2, overlaps hist) ----------------
__global__ void sumsq_kernel(const float* __restrict__ x, long n) {
    int gs = gridDim.x * blockDim.x;
    float s = 0.f;
    for (long i = (long)blockIdx.x * blockDim.x + threadIdx.x; i < n; i += gs) {
        float v = x[i];
        s += v * v;
    }
    __shared__ float sm[256];
    sm[threadIdx.x] = s;
    __syncthreads();
    for (int o = 128; o > 0; o >>= 1) {
        if (threadIdx.x < o) sm[threadIdx.x] += sm[threadIdx.x + o];
        __syncthreads();
    }
    if (threadIdx.x == 0) g_partials[blockIdx.x] = sm[0];
}

__global__ void hist_kernel(const int* __restrict__ dst, int E) {
    int i = blockIdx.x * blockDim.x + threadIdx.x;
    if (i < E) atomicAdd(&g_cnt[dst[i]], 1);
}

// ---------------- scan1: block-local scan + dinv + norm2 finalize ----------------
__global__ void scan1_kernel(int N) {
    __shared__ int sm[256];
    int node = blockIdx.x * 256 + threadIdx.x;
    int c = (node < N) ? g_cnt[node] : 0;
    if (node < N) g_dinv[node] = rsqrtf((float)(c + 1));  // +1 self-loop
    if (blockIdx.x == 0) {
        __shared__ float fm[256];
        fm[threadIdx.x] = g_partials[threadIdx.x] + g_partials[threadIdx.x + 256];
        __syncthreads();
        for (int o = 128; o > 0; o >>= 1) {
            if (threadIdx.x < o) fm[threadIdx.x] += fm[threadIdx.x + o];
            __syncthreads();
        }
        if (threadIdx.x == 0) g_norm2 = fm[0];
    }
    sm[threadIdx.x] = c;
    __syncthreads();
    for (int o = 1; o < 256; o <<= 1) {
        int v = (threadIdx.x >= o) ? sm[threadIdx.x - o] : 0;
        __syncthreads();
        sm[threadIdx.x] += v;
        __syncthreads();
    }
    if (node <= N) g_rowptr[node] = sm[threadIdx.x] - c;
    if (threadIdx.x == 255) g_bsum[blockIdx.x] = sm[255];
}

// ---------------- scan23: per-block re-scan of bsums + finalize rowptr/off/cnt ----------------
__global__ void scan23_kernel(int nb, int N, int E) {
    __shared__ int sm[256];
    int c = (threadIdx.x < nb) ? g_bsum[threadIdx.x] : 0;
    sm[threadIdx.x] = c;
    __syncthreads();
    for (int o = 1; o < 256; o <<= 1) {
        int v = (threadIdx.x >= o) ? sm[threadIdx.x - o] : 0;
        __syncthreads();
        sm[threadIdx.x] += v;
        __syncthreads();
    }
    __syncthreads();
    int boff = (blockIdx.x > 0) ? sm[blockIdx.x - 1] : 0;  // exclusive block offset
    int node = blockIdx.x * 256 + threadIdx.x;
    if (node < N) {
        int r = g_rowptr[node] + boff;
        g_rowptr[node] = r;
        g_off[node] = r;
        g_cnt[node] = 0;  // reset for next graph replay
    } else if (node == N) {
        g_rowptr[N] = E;
    }
}

__global__ void fill_kernel(const int* __restrict__ src, const int* __restrict__ dst, int E) {
    int i = blockIdx.x * blockDim.x + threadIdx.x;
    if (i < E) {
        int pos = atomicAdd(&g_off[dst[i]], 1);
        g_adj[pos] = src[i];
    }
}

// ---------------- fp16 tensor-core GEMM: hs = fp16(dinv[row] * (X @ W)) ----------------
#define SX_STRIDE 120
__global__ void __launch_bounds__(256, 3)
gemm_mma_kernel(const float* __restrict__ X, const float* __restrict__ W,
                __half* __restrict__ hs, int N) {
    extern __shared__ __half smem_h[];
    __half* sX = smem_h;                    // 128 x 120
    __half* sWt = smem_h + 128 * SX_STRIDE; // 104 x 120 (n-major, k contiguous)
    int tid = threadIdx.x;
    int row0 = blockIdx.x * 128;
    const uint2 z2 = make_uint2(0u, 0u);

    for (int i = tid; i < 104 * SX_STRIDE / 4; i += 256)
        ((uint2*)sWt)[i] = z2;

    {
        int r = tid >> 1, h = tid & 1;
        int gr = row0 + r;
        __half* drow = sX + r * SX_STRIDE;
        if (gr < N) {
            const float4* srcp = (const float4*)(X + (size_t)gr * 100);
#pragma unroll
            for (int t = 0; t < 13; t++) {
                int c4 = h * 13 + t;
                if (c4 < 25) {
                    float4 v = __ldg(srcp + c4);
                    __half2 lo = __floats2half2_rn(v.x, v.y);
                    __half2 hi = __floats2half2_rn(v.z, v.w);
                    uint2 u;
                    u.x = *(uint32_t*)&lo; u.y = *(uint32_t*)&hi;
                    *(uint2*)(drow + c4 * 4) = u;
                }
            }
        } else {
#pragma unroll
            for (int t = 0; t < 13; t++) {
                int c4 = h * 13 + t;
                if (c4 < 25) *(uint2*)(drow + c4 * 4) = z2;
            }
        }
        if (h) {
            *(uint2*)(drow + 100) = z2;
            *(uint2*)(drow + 104) = z2;
            *(uint2*)(drow + 108) = z2;
        }
    }
    __syncthreads();

    for (int i = tid; i < 10000; i += 256) {
        int k = i / 100, n = i - k * 100;
        sWt[n * SX_STRIDE + k] = __float2half_rn(__ldg(W + i));
    }
    __syncthreads();

    int warp = tid >> 5, lane = tid & 31;
    int grp = lane >> 2, tig = lane & 3;
    const __half* xw0 = sX + (warp * 16 + grp) * SX_STRIDE;
    const __half* xw1 = xw0 + 8 * SX_STRIDE;

    float acc[13][4];
#pragma unroll
    for (int nt = 0; nt < 13; nt++)
#pragma unroll
        for (int i = 0; i < 4; i++) acc[nt][i] = 0.f;

#pragma unroll
    for (int kc = 0; kc < 7; kc++) {
        int k0 = kc * 16;
        uint32_t a0 = *(const uint32_t*)(xw0 + k0 + 2 * tig);
        uint32_t a1 = *(const uint32_t*)(xw1 + k0 + 2 * tig);
        uint32_t a2 = *(const uint32_t*)(xw0 + k0 + 2 * tig + 8);
        uint32_t a3 = *(const uint32_t*)(xw1 + k0 + 2 * tig + 8);
        const __half* wb = sWt + grp * SX_STRIDE + k0 + 2 * tig;
#pragma unroll
        for (int nt = 0; nt < 13; nt++) {
            uint32_t b0 = *(const uint32_t*)(wb + nt * 8 * SX_STRIDE);
            uint32_t b1 = *(const uint32_t*)(wb + nt * 8 * SX_STRIDE + 8);
            asm volatile(
                "mma.sync.aligned.m16n8k16.row.col.f32.f16.f16.f32 "
                "{%0,%1,%2,%3}, {%4,%5,%6,%7}, {%8,%9}, {%0,%1,%2,%3};"
                : "+f"(acc[nt][0]), "+f"(acc[nt][1]), "+f"(acc[nt][2]), "+f"(acc[nt][3])
                : "r"(a0), "r"(a1), "r"(a2), "r"(a3), "r"(b0), "r"(b1));
        }
    }

    int gr0 = row0 + warp * 16 + grp;
    int gr1 = gr0 + 8;
    float s0 = (gr0 < N) ? g_dinv[gr0] : 0.f;
    float s1 = (gr1 < N) ? g_dinv[gr1] : 0.f;
#pragma unroll
    for (int nt = 0; nt < 13; nt++) {
        int col = nt * 8 + 2 * tig;
        if (gr0 < N) {
            __half2 h = __floats2half2_rn(acc[nt][0] * s0, acc[nt][1] * s0);
            *(__half2*)(hs + (size_t)gr0 * 128 + col) = h;
        }
        if (gr1 < N) {
            __half2 h = __floats2half2_rn(acc[nt][2] * s1, acc[nt][3] * s1);
            *(__half2*)(hs + (size_t)gr1 * 128 + col) = h;
        }
    }
}

// ---- gather helper: add one hs row slice (lane's 4 cols) into sum ----
__device__ __forceinline__ void add_row(float4& sum, const __half* __restrict__ hs,
                                        int node, int lane) {
    uint2 raw = __ldg((const uint2*)(hs + (size_t)node * 128) + lane);
    float2 f0 = __half22float2(*(const __half2*)&raw.x);
    float2 f1 = __half22float2(*(const __half2*)&raw.y);
    sum.x += f0.x; sum.y += f0.y; sum.z += f1.x; sum.w += f1.y;
}

// ---------------- agg after layer0 (2 nodes/warp): acc = (dinv_i*rsqrt(norm2))*sum + cb0 ----------------
__global__ void __launch_bounds__(256)
agg_kernel(const __half* __restrict__ hs, float* __restrict__ acc,
           const int* __restrict__ rowptr, const int* __restrict__ adj,
           const float* __restrict__ cb, int N) {
    int warp = (blockIdx.x * 256 + threadIdx.x) >> 5;
    int lane = threadIdx.x & 31;
    int n0 = warp * 2, n1 = n0 + 1;
    if (n0 >= N) return;
    bool has1 = (n1 < N);
    bool act = lane < 25;

    float4 s0 = make_float4(0.f, 0.f, 0.f, 0.f);
    float4 s1 = make_float4(0.f, 0.f, 0.f, 0.f);
    if (act) {
        add_row(s0, hs, n0, lane);
        if (has1) add_row(s1, hs, n1, lane);
    }

    int b0 = rowptr[n0], e0 = rowptr[n0 + 1];
    int b1 = has1 ? e0 : 0, e1 = has1 ? rowptr[n1 + 1] : 0;  // CSR contiguity: rowptr[n1]==e0

    while (b0 < e0 || b1 < e1) {
        int my0 = (b0 + lane < e0) ? __ldg(adj + b0 + lane) : 0;
        int my1 = (b1 + lane < e1) ? __ldg(adj + b1 + lane) : 0;
        int c0 = max(0, min(32, e0 - b0));
        int c1 = max(0, min(32, e1 - b1));
        int cm = max(c0, c1);
#pragma unroll 4
        for (int j = 0; j < cm; j++) {
            int t0 = __shfl_sync(0xffffffffu, my0, j);
            int t1 = __shfl_sync(0xffffffffu, my1, j);
            if (act && j < c0) add_row(s0, hs, t0, lane);
            if (act && j < c1) add_row(s1, hs, t1, lane);
        }
        b0 += 32; b1 += 32;
    }

    if (act) {
        float nm = rsqrtf(g_norm2);
        float4 b = __ldg((const float4*)cb + lane);
        {
            float os = g_dinv[n0] * nm;
            float4 o = make_float4(s0.x * os + b.x, s0.y * os + b.y,
                                   s0.z * os + b.z, s0.w * os + b.w);
            *((float4*)(acc + (size_t)n0 * 100) + lane) = o;
        }
        if (has1) {
            float os = g_dinv[n1] * nm;
            float4 o = make_float4(s1.x * os + b.x, s1.y * os + b.y,
                                   s1.z * os + b.z, s1.w * os + b.w);
            *((float4*)(acc + (size_t)n1 * 100) + lane) = o;
        }
    }
}

// ---------------- fused agg after layer1 + MLP head (2 nodes/warp) ----------------
__global__ void __launch_bounds__(256)
agg_head_kernel(const __half* __restrict__ hs,
                const int* __restrict__ rowptr, const int* __restrict__ adj,
                const float* __restrict__ cb,
                const float* __restrict__ W0, const float* __restrict__ b0,
                const float* __restrict__ W1, const float* __restrict__ b1,
                float* __restrict__ out, int N) {
    __shared__ float w0t[10 * 104];  // w0t[j*104+k] = W0[k*10+j]
    __shared__ float b0s[10];
    __shared__ float w1s[10];
    __shared__ float b1v;
    int tid = threadIdx.x;

    for (int i = tid; i < 1000; i += 256) {
        int k = i / 10, j = i - k * 10;
        w0t[j * 104 + k] = __ldg(W0 + i);
    }
    if (tid < 10) { b0s[tid] = __ldg(b0 + tid); w1s[tid] = __ldg(W1 + tid); }
    if (tid == 0) b1v = __ldg(b1);
    __syncthreads();

    int warp = (blockIdx.x * 256 + tid) >> 5;
    int lane = tid & 31;
    int n0 = warp * 2, n1 = n0 + 1;
    if (n0 >= N) return;
    bool has1 = (n1 < N);
    bool act = lane < 25;

    float4 s0 = make_float4(0.f, 0.f, 0.f, 0.f);
    float4 s1 = make_float4(0.f, 0.f, 0.f, 0.f);
    if (act) {
        add_row(s0, hs, n0, lane);
        if (has1) add_row(s1, hs, n1, lane);
    }

    int rb0 = rowptr[n0], re0 = rowptr[n0 + 1];
    int rb1 = has1 ? re0 : 0, re1 = has1 ? rowptr[n1 + 1] : 0;

    while (rb0 < re0 || rb1 < re1) {
        int my0 = (rb0 + lane < re0) ? __ldg(adj + rb0 + lane) : 0;
        int my1 = (rb1 + lane < re1) ? __ldg(adj + rb1 + lane) : 0;
        int c0 = max(0, min(32, re0 - rb0));
        int c1 = max(0, min(32, re1 - rb1));
        int cm = max(c0, c1);
#pragma unroll 4
        for (int j = 0; j < cm; j++) {
            int t0 = __shfl_sync(0xffffffffu, my0, j);
            int t1 = __shfl_sync(0xffffffffu, my1, j);
            if (act && j < c0) add_row(s0, hs, t0, lane);
            if (act && j < c1) add_row(s1, hs, t1, lane);
        }
        rb0 += 32; rb1 += 32;
    }

    float4 bc = make_float4(0.f, 0.f, 0.f, 0.f);
    if (act) bc = __ldg((const float4*)cb + lane);

#pragma unroll
    for (int nn = 0; nn < 2; nn++) {
        int node = nn ? n1 : n0;
        if (nn && !has1) break;
        float4 sv = nn ? s1 : s0;
        float4 x2 = make_float4(0.f, 0.f, 0.f, 0.f);
        if (act) {
            float di = g_dinv[node];
            x2.x = di * sv.x + bc.x; x2.y = di * sv.y + bc.y;
            x2.z = di * sv.z + bc.z; x2.w = di * sv.w + bc.w;
        }
        float p[10];
#pragma unroll
        for (int j = 0; j < 10; j++) {
            float4 w = make_float4(0.f, 0.f, 0.f, 0.f);
            if (act) w = *(const float4*)(w0t + j * 104 + 4 * lane);
            p[j] = x2.x * w.x + x2.y * w.y + x2.z * w.z + x2.w * w.w;
        }
#pragma unroll
        for (int j = 0; j < 10; j++) {
#pragma unroll
            for (int off = 16; off > 0; off >>= 1)
                p[j] += __shfl_xor_sync(0xffffffffu, p[j], off);
        }
        if (lane == 0) {
            float o = b1v;
#pragma unroll
            for (int j = 0; j < 10; j++) o += fmaxf(p[j] + b0s[j], 0.f) * w1s[j];
            out[node] = o;
        }
    }
}

extern "C" void kernel_launch(void* const* d_in, const int* in_sizes, int n_in,
                              void* d_out, int out_size) {
    const float* x   = (const float*)d_in[0];
    const int*   ei  = (const int*)d_in[1];
    const float* W0  = (const float*)d_in[2];
    const float* cb0 = (const float*)d_in[3];
    const float* W1  = (const float*)d_in[4];
    const float* cb1 = (const float*)d_in[5];
    const float* lW0 = (const float*)d_in[6];
    const float* lb0 = (const float*)d_in[7];
    const float* lW1 = (const float*)d_in[8];
    const float* lb1 = (const float*)d_in[9];
    float* out = (float*)d_out;

    int N = in_sizes[0] / 100;
    int E = in_sizes[1] / 2;
    const int* src = ei;
    const int* dst = ei + E;

    size_t gemm_smem = (128 + 104) * SX_STRIDE * sizeof(__half);  // 55.7 KB -> 3 blocks/SM
    cudaFuncSetAttribute(gemm_mma_kernel,
                         cudaFuncAttributeMaxDynamicSharedMemorySize, (int)gemm_smem);

    __half* hs;
    float* acc;
    int *rowptr, *adj;
    cudaGetSymbolAddress((void**)&hs, g_hs);
    cudaGetSymbolAddress((void**)&acc, g_acc);
    cudaGetSymbolAddress((void**)&rowptr, g_rowptr);
    cudaGetSymbolAddress((void**)&adj, g_adj);

    cudaStream_t s2;
    cudaStreamCreateWithFlags(&s2, cudaStreamNonBlocking);
    cudaEvent_t ev0, evH, evD, ev1;
    cudaEventCreateWithFlags(&ev0, cudaEventDisableTiming);
    cudaEventCreateWithFlags(&evH, cudaEventDisableTiming);
    cudaEventCreateWithFlags(&evD, cudaEventDisableTiming);
    cudaEventCreateWithFlags(&ev1, cudaEventDisableTiming);

    cudaEventRecord(ev0, 0);
    cudaStreamWaitEvent(s2, ev0, 0);

    // overlap: sumsq (s2) || hist (default)
    long n_elem = (long)N * 100;
    sumsq_kernel<<<512, 256, 0, s2>>>(x, n_elem);
    hist_kernel<<<(E + 255) / 256, 256>>>(dst, E);
    cudaEventRecord(evH, 0);
    cudaStreamWaitEvent(s2, evH, 0);

    // s2: scan1 (local scan + dinv + norm2) -> scan23 -> fill
    int nscan = (N + 256) / 256;
    scan1_kernel<<<nscan, 256, 0, s2>>>(N);
    cudaEventRecord(evD, s2);
    scan23_kernel<<<nscan, 256, 0, s2>>>(nscan, N, E);
    fill_kernel<<<(E + 255) / 256, 256, 0, s2>>>(src, dst, E);
    cudaEventRecord(ev1, s2);

    // default: gemm0 (needs dinv) overlaps scan23 + fill
    cudaStreamWaitEvent(0, evD, 0);
    int gblocks = (N + 127) / 128;
    gemm_mma_kernel<<<gblocks, 256, gemm_smem>>>(x, W0, hs, N);

    cudaStreamWaitEvent(0, ev1, 0);  // join

    int ablocks = (N + 15) / 16;  // 8 warps/block, 2 nodes/warp
    agg_kernel<<<ablocks, 256>>>(hs, acc, rowptr, adj, cb0, N);
    gemm_mma_kernel<<<gblocks, 256, gemm_smem>>>(acc, W1, hs, N);
    agg_head_kernel<<<ablocks, 256>>>(hs, rowptr, adj, cb1, lW0, lb0, lW1, lb1, out, N);
}

// round 16
// speedup vs baseline: 1.0282x; 1.0282x over previous
#include <cuda_runtime.h>
#include <cuda_fp16.h>
#include <math.h>
#include <stdint.h>

// ---------------- scratch (no allocation allowed) ----------------
__device__ __half g_hs[6400000];   // 50000 x 128 halves (256B-aligned rows)
__device__ __half g_x1[6400000];   // layer-1 input, fp16, 128-stride padded (cols 100..127 = 0)
__device__ float  g_dinv[50048];
__device__ int    g_cnt[50048];    // statically zero; re-zeroed by scan23 each call
__device__ int    g_rowptr[50049];
__device__ int    g_off[50049];
__device__ int    g_adj[800064];
__device__ int    g_bsum[256];
__device__ float  g_partials[512];
__device__ float  g_norm2;

// ---------------- ||x||^2 partial sums (s2, overlaps hist) ----------------
__global__ void sumsq_kernel(const float* __restrict__ x, long n) {
    int gs = gridDim.x * blockDim.x;
    float s = 0.f;
    for (long i = (long)blockIdx.x * blockDim.x + threadIdx.x; i < n; i += gs) {
        float v = x[i];
        s += v * v;
    }
    __shared__ float sm[256];
    sm[threadIdx.x] = s;
    __syncthreads();
    for (int o = 128; o > 0; o >>= 1) {
        if (threadIdx.x < o) sm[threadIdx.x] += sm[threadIdx.x + o];
        __syncthreads();
    }
    if (threadIdx.x == 0) g_partials[blockIdx.x] = sm[0];
}

__global__ void hist_kernel(const int* __restrict__ dst, int E) {
    int i = blockIdx.x * blockDim.x + threadIdx.x;
    if (i < E) atomicAdd(&g_cnt[dst[i]], 1);
}

// ---------------- scan1: block-local scan + dinv + norm2 finalize ----------------
__global__ void scan1_kernel(int N) {
    __shared__ int sm[256];
    int node = blockIdx.x * 256 + threadIdx.x;
    int c = (node < N) ? g_cnt[node] : 0;
    if (node < N) g_dinv[node] = rsqrtf((float)(c + 1));  // +1 self-loop
    if (blockIdx.x == 0) {
        __shared__ float fm[256];
        fm[threadIdx.x] = g_partials[threadIdx.x] + g_partials[threadIdx.x + 256];
        __syncthreads();
        for (int o = 128; o > 0; o >>= 1) {
            if (threadIdx.x < o) fm[threadIdx.x] += fm[threadIdx.x + o];
            __syncthreads();
        }
        if (threadIdx.x == 0) g_norm2 = fm[0];
    }
    sm[threadIdx.x] = c;
    __syncthreads();
    for (int o = 1; o < 256; o <<= 1) {
        int v = (threadIdx.x >= o) ? sm[threadIdx.x - o] : 0;
        __syncthreads();
        sm[threadIdx.x] += v;
        __syncthreads();
    }
    if (node <= N) g_rowptr[node] = sm[threadIdx.x] - c;
    if (threadIdx.x == 255) g_bsum[blockIdx.x] = sm[255];
}

// ---------------- scan23: per-block re-scan of bsums + finalize rowptr/off/cnt ----------------
__global__ void scan23_kernel(int nb, int N, int E) {
    __shared__ int sm[256];
    int c = (threadIdx.x < nb) ? g_bsum[threadIdx.x] : 0;
    sm[threadIdx.x] = c;
    __syncthreads();
    for (int o = 1; o < 256; o <<= 1) {
        int v = (threadIdx.x >= o) ? sm[threadIdx.x - o] : 0;
        __syncthreads();
        sm[threadIdx.x] += v;
        __syncthreads();
    }
    __syncthreads();
    int boff = (blockIdx.x > 0) ? sm[blockIdx.x - 1] : 0;  // exclusive block offset
    int node = blockIdx.x * 256 + threadIdx.x;
    if (node < N) {
        int r = g_rowptr[node] + boff;
        g_rowptr[node] = r;
        g_off[node] = r;
        g_cnt[node] = 0;  // reset for next graph replay
    } else if (node == N) {
        g_rowptr[N] = E;
    }
}

__global__ void fill_kernel(const int* __restrict__ src, const int* __restrict__ dst, int E) {
    int i = blockIdx.x * blockDim.x + threadIdx.x;
    if (i < E) {
        int pos = atomicAdd(&g_off[dst[i]], 1);
        g_adj[pos] = src[i];
    }
}

// ---------------- fp16 tensor-core GEMM: hs = fp16(dinv[row] * (X @ W)) ----------------
// HALF_IN=0: X is fp32, row stride 100. HALF_IN=1: X is fp16, row stride 128 (pre-padded).
#define SX_STRIDE 120
template<int HALF_IN>
__global__ void __launch_bounds__(256, 3)
gemm_mma_kernel(const void* __restrict__ Xv, const float* __restrict__ W,
                __half* __restrict__ hs, int N) {
    extern __shared__ __half smem_h[];
    __half* sX = smem_h;                    // 128 x 120
    __half* sWt = smem_h + 128 * SX_STRIDE; // 104 x 120 (n-major, k contiguous)
    int tid = threadIdx.x;
    int row0 = blockIdx.x * 128;
    const uint2 z2 = make_uint2(0u, 0u);

    for (int i = tid; i < 104 * SX_STRIDE / 4; i += 256)
        ((uint2*)sWt)[i] = z2;

    {
        int r = tid >> 1, h = tid & 1;
        int gr = row0 + r;
        __half* drow = sX + r * SX_STRIDE;
        if (gr < N) {
            if (HALF_IN) {
                const uint2* srcp = (const uint2*)((const __half*)Xv + (size_t)gr * 128);
#pragma unroll
                for (int t = 0; t < 13; t++) {
                    int c4 = h * 13 + t;
                    if (c4 < 25) *(uint2*)(drow + c4 * 4) = __ldg(srcp + c4);
                }
            } else {
                const float4* srcp = (const float4*)((const float*)Xv + (size_t)gr * 100);
#pragma unroll
                for (int t = 0; t < 13; t++) {
                    int c4 = h * 13 + t;
                    if (c4 < 25) {
                        float4 v = __ldg(srcp + c4);
                        __half2 lo = __floats2half2_rn(v.x, v.y);
                        __half2 hi = __floats2half2_rn(v.z, v.w);
                        uint2 u;
                        u.x = *(uint32_t*)&lo; u.y = *(uint32_t*)&hi;
                        *(uint2*)(drow + c4 * 4) = u;
                    }
                }
            }
        } else {
#pragma unroll
            for (int t = 0; t < 13; t++) {
                int c4 = h * 13 + t;
                if (c4 < 25) *(uint2*)(drow + c4 * 4) = z2;
            }
        }
        if (h) {
            *(uint2*)(drow + 100) = z2;
            *(uint2*)(drow + 104) = z2;
            *(uint2*)(drow + 108) = z2;
        }
    }
    __syncthreads();

    for (int i = tid; i < 10000; i += 256) {
        int k = i / 100, n = i - k * 100;
        sWt[n * SX_STRIDE + k] = __float2half_rn(__ldg(W + i));
    }
    __syncthreads();

    int warp = tid >> 5, lane = tid & 31;
    int grp = lane >> 2, tig = lane & 3;
    const __half* xw0 = sX + (warp * 16 + grp) * SX_STRIDE;
    const __half* xw1 = xw0 + 8 * SX_STRIDE;

    float acc[13][4];
#pragma unroll
    for (int nt = 0; nt < 13; nt++)
#pragma unroll
        for (int i = 0; i < 4; i++) acc[nt][i] = 0.f;

#pragma unroll
    for (int kc = 0; kc < 7; kc++) {
        int k0 = kc * 16;
        uint32_t a0 = *(const uint32_t*)(xw0 + k0 + 2 * tig);
        uint32_t a1 = *(const uint32_t*)(xw1 + k0 + 2 * tig);
        uint32_t a2 = *(const uint32_t*)(xw0 + k0 + 2 * tig + 8);
        uint32_t a3 = *(const uint32_t*)(xw1 + k0 + 2 * tig + 8);
        const __half* wb = sWt + grp * SX_STRIDE + k0 + 2 * tig;
#pragma unroll
        for (int nt = 0; nt < 13; nt++) {
            uint32_t b0 = *(const uint32_t*)(wb + nt * 8 * SX_STRIDE);
            uint32_t b1 = *(const uint32_t*)(wb + nt * 8 * SX_STRIDE + 8);
            asm volatile(
                "mma.sync.aligned.m16n8k16.row.col.f32.f16.f16.f32 "
                "{%0,%1,%2,%3}, {%4,%5,%6,%7}, {%8,%9}, {%0,%1,%2,%3};"
                : "+f"(acc[nt][0]), "+f"(acc[nt][1]), "+f"(acc[nt][2]), "+f"(acc[nt][3])
                : "r"(a0), "r"(a1), "r"(a2), "r"(a3), "r"(b0), "r"(b1));
        }
    }

    int gr0 = row0 + warp * 16 + grp;
    int gr1 = gr0 + 8;
    float s0 = (gr0 < N) ? g_dinv[gr0] : 0.f;
    float s1 = (gr1 < N) ? g_dinv[gr1] : 0.f;
#pragma unroll
    for (int nt = 0; nt < 13; nt++) {
        int col = nt * 8 + 2 * tig;
        if (gr0 < N) {
            __half2 h = __floats2half2_rn(acc[nt][0] * s0, acc[nt][1] * s0);
            *(__half2*)(hs + (size_t)gr0 * 128 + col) = h;
        }
        if (gr1 < N) {
            __half2 h = __floats2half2_rn(acc[nt][2] * s1, acc[nt][3] * s1);
            *(__half2*)(hs + (size_t)gr1 * 128 + col) = h;
        }
    }
}

// ---------------- agg after layer0: x1 = fp16((dinv_i*rsqrt(norm2))*sum + cb0) ----------------
// [R12/R14-proven loop: 25 active lanes x uint2; output now fp16 padded 128-stride]
__global__ void __launch_bounds__(256)
agg_kernel(const __half* __restrict__ hs, __half* __restrict__ x1,
           const int* __restrict__ rowptr, const int* __restrict__ adj,
           const float* __restrict__ cb, int N) {
    int node = (blockIdx.x * 256 + threadIdx.x) >> 5;
    int lane = threadIdx.x & 31;
    if (node >= N) return;
    bool act = lane < 25;

    float4 sum = make_float4(0.f, 0.f, 0.f, 0.f);
    if (act) {
        uint2 raw = __ldg((const uint2*)(hs + (size_t)node * 128) + lane);
        float2 f0 = __half22float2(*(const __half2*)&raw.x);
        float2 f1 = __half22float2(*(const __half2*)&raw.y);
        sum.x = f0.x; sum.y = f0.y; sum.z = f1.x; sum.w = f1.y;
    }

    int beg = rowptr[node];
    int end = rowptr[node + 1];
    for (int base = beg; base < end; base += 32) {
        int idx = base + lane;
        int my = (idx < end) ? __ldg(adj + idx) : 0;
        int cnt = min(32, end - base);
#pragma unroll 8
        for (int j = 0; j < cnt; j++) {
            int s = __shfl_sync(0xffffffffu, my, j);
            if (act) {
                uint2 raw = __ldg((const uint2*)(hs + (size_t)s * 128) + lane);
                float2 f0 = __half22float2(*(const __half2*)&raw.x);
                float2 f1 = __half22float2(*(const __half2*)&raw.y);
                sum.x += f0.x; sum.y += f0.y; sum.z += f1.x; sum.w += f1.y;
            }
        }
    }
    // lanes 25..31 write zero pads for cols 100..127
    __half* xrow = x1 + (size_t)node * 128;
    if (act) {
        float os = g_dinv[node] * rsqrtf(g_norm2);
        float4 b = __ldg((const float4*)cb + lane);
        __half2 lo = __floats2half2_rn(sum.x * os + b.x, sum.y * os + b.y);
        __half2 hi = __floats2half2_rn(sum.z * os + b.z, sum.w * os + b.w);
        uint2 u;
        u.x = *(uint32_t*)&lo; u.y = *(uint32_t*)&hi;
        *((uint2*)xrow + lane) = u;
    } else {
        *((uint2*)xrow + lane) = make_uint2(0u, 0u);
    }
}

// ---------------- fused agg after layer1 + MLP head  [R12/R14-proven] ----------------
__global__ void __launch_bounds__(256)
agg_head_kernel(const __half* __restrict__ hs,
                const int* __restrict__ rowptr, const int* __restrict__ adj,
                const float* __restrict__ cb,
                const float* __restrict__ W0, const float* __restrict__ b0,
                const float* __restrict__ W1, const float* __restrict__ b1,
                float* __restrict__ out, int N) {
    __shared__ float w0t[10 * 104];  // w0t[j*104+k] = W0[k*10+j]
    __shared__ float b0s[10];
    __shared__ float w1s[10];
    __shared__ float b1v;
    int tid = threadIdx.x;

    for (int i = tid; i < 1000; i += 256) {
        int k = i / 10, j = i - k * 10;
        w0t[j * 104 + k] = __ldg(W0 + i);
    }
    if (tid < 10) { b0s[tid] = __ldg(b0 + tid); w1s[tid] = __ldg(W1 + tid); }
    if (tid == 0) b1v = __ldg(b1);
    __syncthreads();

    int node = (blockIdx.x * 256 + tid) >> 5;
    int lane = tid & 31;
    if (node >= N) return;
    bool act = lane < 25;

    float4 sum = make_float4(0.f, 0.f, 0.f, 0.f);
    if (act) {
        uint2 raw = __ldg((const uint2*)(hs + (size_t)node * 128) + lane);
        float2 f0 = __half22float2(*(const __half2*)&raw.x);
        float2 f1 = __half22float2(*(const __half2*)&raw.y);
        sum.x = f0.x; sum.y = f0.y; sum.z = f1.x; sum.w = f1.y;
    }
    int beg = rowptr[node];
    int end = rowptr[node + 1];
    for (int base = beg; base < end; base += 32) {
        int idx = base + lane;
        int my = (idx < end) ? __ldg(adj + idx) : 0;
        int cnt = min(32, end - base);
#pragma unroll 8
        for (int j = 0; j < cnt; j++) {
            int s = __shfl_sync(0xffffffffu, my, j);
            if (act) {
                uint2 raw = __ldg((const uint2*)(hs + (size_t)s * 128) + lane);
                float2 f0 = __half22float2(*(const __half2*)&raw.x);
                float2 f1 = __half22float2(*(const __half2*)&raw.y);
                sum.x += f0.x; sum.y += f0.y; sum.z += f1.x; sum.w += f1.y;
            }
        }
    }

    float4 x2 = make_float4(0.f, 0.f, 0.f, 0.f);
    if (act) {
        float di = g_dinv[node];
        float4 b = __ldg((const float4*)cb + lane);
        x2.x = di * sum.x + b.x; x2.y = di * sum.y + b.y;
        x2.z = di * sum.z + b.z; x2.w = di * sum.w + b.w;
    }

    float p[10];
#pragma unroll
    for (int j = 0; j < 10; j++) {
        float4 w = make_float4(0.f, 0.f, 0.f, 0.f);
        if (act) w = *(const float4*)(w0t + j * 104 + 4 * lane);
        p[j] = x2.x * w.x + x2.y * w.y + x2.z * w.z + x2.w * w.w;
    }
#pragma unroll
    for (int j = 0; j < 10; j++) {
#pragma unroll
        for (int off = 16; off > 0; off >>= 1)
            p[j] += __shfl_xor_sync(0xffffffffu, p[j], off);
    }
    if (lane == 0) {
        float o = b1v;
#pragma unroll
        for (int j = 0; j < 10; j++) o += fmaxf(p[j] + b0s[j], 0.f) * w1s[j];
        out[node] = o;
    }
}

extern "C" void kernel_launch(void* const* d_in, const int* in_sizes, int n_in,
                              void* d_out, int out_size) {
    const float* x   = (const float*)d_in[0];
    const int*   ei  = (const int*)d_in[1];
    const float* W0  = (const float*)d_in[2];
    const float* cb0 = (const float*)d_in[3];
    const float* W1  = (const float*)d_in[4];
    const float* cb1 = (const float*)d_in[5];
    const float* lW0 = (const float*)d_in[6];
    const float* lb0 = (const float*)d_in[7];
    const float* lW1 = (const float*)d_in[8];
    const float* lb1 = (const float*)d_in[9];
    float* out = (float*)d_out;

    int N = in_sizes[0] / 100;
    int E = in_sizes[1] / 2;
    const int* src = ei;
    const int* dst = ei + E;

    size_t gemm_smem = (128 + 104) * SX_STRIDE * sizeof(__half);  // 55.7 KB -> 3 blocks/SM
    cudaFuncSetAttribute(gemm_mma_kernel<0>,
                         cudaFuncAttributeMaxDynamicSharedMemorySize, (int)gemm_smem);
    cudaFuncSetAttribute(gemm_mma_kernel<1>,
                         cudaFuncAttributeMaxDynamicSharedMemorySize, (int)gemm_smem);

    __half *hs, *x1;
    int *rowptr, *adj;
    cudaGetSymbolAddress((void**)&hs, g_hs);
    cudaGetSymbolAddress((void**)&x1, g_x1);
    cudaGetSymbolAddress((void**)&rowptr, g_rowptr);
    cudaGetSymbolAddress((void**)&adj, g_adj);

    cudaStream_t s2;
    cudaStreamCreateWithFlags(&s2, cudaStreamNonBlocking);
    cudaEvent_t ev0, evH, evD, ev1;
    cudaEventCreateWithFlags(&ev0, cudaEventDisableTiming);
    cudaEventCreateWithFlags(&evH, cudaEventDisableTiming);
    cudaEventCreateWithFlags(&evD, cudaEventDisableTiming);
    cudaEventCreateWithFlags(&ev1, cudaEventDisableTiming);

    cudaEventRecord(ev0, 0);
    cudaStreamWaitEvent(s2, ev0, 0);

    // overlap: sumsq (s2) || hist (default)
    long n_elem = (long)N * 100;
    sumsq_kernel<<<512, 256, 0, s2>>>(x, n_elem);
    hist_kernel<<<(E + 255) / 256, 256>>>(dst, E);
    cudaEventRecord(evH, 0);
    cudaStreamWaitEvent(s2, evH, 0);

    // s2: scan1 (local scan + dinv + norm2) -> scan23 -> fill
    int nscan = (N + 256) / 256;
    scan1_kernel<<<nscan, 256, 0, s2>>>(N);
    cudaEventRecord(evD, s2);
    scan23_kernel<<<nscan, 256, 0, s2>>>(nscan, N, E);
    fill_kernel<<<(E + 255) / 256, 256, 0, s2>>>(src, dst, E);
    cudaEventRecord(ev1, s2);

    // default: gemm0 (needs dinv) overlaps scan23 + fill
    cudaStreamWaitEvent(0, evD, 0);
    int gblocks = (N + 127) / 128;
    gemm_mma_kernel<0><<<gblocks, 256, gemm_smem>>>(x, W0, hs, N);

    cudaStreamWaitEvent(0, ev1, 0);  // join

    int ablocks = (N + 7) / 8;
    agg_kernel<<<ablocks, 256>>>(hs, x1, rowptr, adj, cb0, N);
    gemm_mma_kernel<1><<<gblocks, 256, gemm_smem>>>(x1, W1, hs, N);
    agg_head_kernel<<<ablocks, 256>>>(hs, rowptr, adj, cb1, lW0, lb0, lW1, lb1, out, N);
}